// round 11
// baseline (speedup 1.0000x reference)
#include <cuda_runtime.h>
#include <cuda_bf16.h>
#include <cstdint>

#define N_NODES 200000
#define ATTD 16

// Per-node accumulator: {sum_exp, sum_exp*vx, sum_exp*vy, pad}
// Zero-initialized at module load; node_kernel re-zeroes after consuming,
// so every kernel_launch invocation (correctness run + each graph replay)
// starts from a zeroed accumulator. No memset needed.
__device__ float4 g_acc[N_NODES];

// ---------- packed f32x2 helpers ----------
typedef unsigned long long f2;

__device__ __forceinline__ f2 pk(float a, float b) {
    f2 r; asm("mov.b64 %0, {%1, %2};" : "=l"(r) : "f"(a), "f"(b)); return r;
}
__device__ __forceinline__ void upk(f2 v, float& a, float& b) {
    asm("mov.b64 {%0, %1}, %2;" : "=f"(a), "=f"(b) : "l"(v));
}
__device__ __forceinline__ f2 fma2(f2 a, f2 b, f2 c) {
    f2 r; asm("fma.rn.f32x2 %0, %1, %2, %3;" : "=l"(r) : "l"(a), "l"(b), "l"(c)); return r;
}
__device__ __forceinline__ f2 mul2(f2 a, f2 b) {
    f2 r; asm("mul.rn.f32x2 %0, %1, %2;" : "=l"(r) : "l"(a), "l"(b)); return r;
}
__device__ __forceinline__ f2 add2(f2 a, f2 b) {
    f2 r; asm("add.rn.f32x2 %0, %1, %2;" : "=l"(r) : "l"(a), "l"(b)); return r;
}
__device__ __forceinline__ float tanh_ap(float x) {
    float y; asm("tanh.approx.f32 %0, %1;" : "=f"(y) : "f"(x)); return y;
}
__device__ __forceinline__ float rcp_ap(float x) {
    float y; asm("rcp.approx.f32 %0, %1;" : "=f"(y) : "f"(x)); return y;
}
__device__ __forceinline__ float rsqrt_ap(float x) {
    float y; asm("rsqrt.approx.f32 %0, %1;" : "=f"(y) : "f"(x)); return y;
}

struct EdgePair {
    f2 VX, VY;      // tangent vectors for 2 edges
};

// log-map for 2 edges packed in f32x2
__device__ __forceinline__ EdgePair logmap2(float2 xi0, float2 xi1,
                                            float2 xj0, float2 xj1) {
    const f2 ONE  = pk(1.f, 1.f);
    const f2 NEG1 = pk(-1.f, -1.f);
    const f2 TWO  = pk(2.f, 2.f);

    f2 AX  = pk(-xi0.x, -xi1.x);
    f2 AY  = pk(-xi0.y, -xi1.y);
    f2 XJX = pk(xj0.x, xj1.x);
    f2 XJY = pk(xj0.y, xj1.y);

    f2 DN = fma2(AY, XJY, mul2(AX, XJX));
    f2 AA = fma2(AY, AY, mul2(AX, AX));
    f2 BB = fma2(XJY, XJY, mul2(XJX, XJX));
    f2 NA = fma2(TWO, DN, add2(BB, ONE));       // 1 + 2 a.b + |b|^2
    f2 NB = fma2(AA, NEG1, ONE);                // 1 - |xi|^2  > 0.75, no clamp
    f2 DEN = fma2(TWO, DN, fma2(AA, BB, ONE));  // > 0.5, no clamp

    float d0, d1;
    upk(DEN, d0, d1);
    f2 IDEN = pk(rcp_ap(d0), rcp_ap(d1));

    f2 UX = mul2(fma2(NA, AX, mul2(NB, XJX)), IDEN);
    f2 UY = mul2(fma2(NA, AY, mul2(NB, XJY)), IDEN);

    f2 UN2 = fma2(UY, UY, mul2(UX, UX));
    float un20, un21;
    upk(UN2, un20, un21);
    un20 = fmaxf(un20, 1e-30f);
    un21 = fmaxf(un21, 1e-30f);
    float ir0 = rsqrt_ap(un20), ir1 = rsqrt_ap(un21);
    float z0 = fminf(un20 * ir0, 1.f - 1e-5f);
    float z1 = fminf(un21 * ir1, 1.f - 1e-5f);
    float at0 = 0.5f * __logf((1.f + z0) * rcp_ap(1.f - z0));  // atanh
    float at1 = 0.5f * __logf((1.f + z1) * rcp_ap(1.f - z1));

    f2 FACT = mul2(mul2(NB, pk(at0, at1)), pk(ir0, ir1));
    EdgePair ep;
    ep.VX = mul2(FACT, UX);
    ep.VY = mul2(FACT, UY);
    return ep;
}

__global__ void __launch_bounds__(256)
edge_kernel(const float2* __restrict__ x,
            const int4* __restrict__ row4,
            const int4* __restrict__ col4,
            const float* __restrict__ W1,
            const float* __restrict__ b1,
            const float* __restrict__ W2,
            int E) {
    // Broadcast-packed weights in shared memory (LDS.64 broadcast, conflict-free)
    __shared__ f2 sw1x[ATTD], sw1y[ATTD], sb1[ATTD], shw2[ATTD];
    if (threadIdx.x < ATTD) {
        int k = threadIdx.x;
        float a = __ldg(W1 + k);
        float b = __ldg(W1 + ATTD + k);
        float c = __ldg(b1 + k);
        float d = 0.5f * __ldg(W2 + k);
        sw1x[k] = pk(a, a);
        sw1y[k] = pk(b, b);
        sb1[k]  = pk(c, c);
        shw2[k] = pk(d, d);
    }
    __syncthreads();

    const f2 G0 = pk(0.7978845608028654f, 0.7978845608028654f);
    const f2 G1 = pk(0.0356774081363f, 0.0356774081363f);  // G0*0.044715

    int nquads = E >> 2;   // E divisible by 4
    int stride = gridDim.x * blockDim.x;
    for (int i = blockIdx.x * blockDim.x + threadIdx.x; i < nquads; i += stride) {
        int4 rr = __ldg(row4 + i);
        int4 cc = __ldg(col4 + i);

        // 8 independent gathers issued up front (L2-resident, MLP=8)
        float2 xiA = __ldg(x + rr.x);
        float2 xiB = __ldg(x + rr.y);
        float2 xiC = __ldg(x + rr.z);
        float2 xiD = __ldg(x + rr.w);
        float2 xjA = __ldg(x + cc.x);
        float2 xjB = __ldg(x + cc.y);
        float2 xjC = __ldg(x + cc.z);
        float2 xjD = __ldg(x + cc.w);

        EdgePair p0 = logmap2(xiA, xiB, xjA, xjB);
        EdgePair p1 = logmap2(xiC, xiD, xjC, xjD);

        // ---- MLP scores: two packed pipelines interleaved ----
        f2 S0 = pk(0.f, 0.f);
        f2 S1 = pk(0.f, 0.f);
#pragma unroll
        for (int k = 0; k < ATTD; k++) {
            f2 w1xk = sw1x[k], w1yk = sw1y[k], b1k = sb1[k], w2k = shw2[k];
            f2 PRE0 = fma2(p0.VX, w1xk, fma2(p0.VY, w1yk, b1k));
            f2 PRE1 = fma2(p1.VX, w1xk, fma2(p1.VY, w1yk, b1k));
            f2 ARG0 = mul2(fma2(mul2(PRE0, PRE0), G1, G0), PRE0);
            f2 ARG1 = mul2(fma2(mul2(PRE1, PRE1), G1, G0), PRE1);
            float a0, a1, a2, a3;
            upk(ARG0, a0, a1);
            upk(ARG1, a2, a3);
            f2 TH0 = pk(tanh_ap(a0), tanh_ap(a1));
            f2 TH1 = pk(tanh_ap(a2), tanh_ap(a3));
            f2 T0 = mul2(PRE0, w2k);
            f2 T1 = mul2(PRE1, w2k);
            S0 = add2(S0, T0);
            S1 = add2(S1, T1);
            S0 = fma2(T0, TH0, S0);
            S1 = fma2(T1, TH1, S1);
        }

        float s0, s1, s2, s3;
        upk(S0, s0, s1);
        upk(S1, s2, s3);
        float vx0, vx1, vx2, vx3, vy0, vy1, vy2, vy3;
        upk(p0.VX, vx0, vx1);
        upk(p0.VY, vy0, vy1);
        upk(p1.VX, vx2, vx3);
        upk(p1.VY, vy2, vy3);

        float ex0 = __expf(s0);
        float ex1 = __expf(s1);
        float ex2 = __expf(s2);
        float ex3 = __expf(s3);

        asm volatile("red.global.add.v4.f32 [%0], {%1, %2, %3, %4};"
                     :: "l"(&g_acc[rr.x]), "f"(ex0), "f"(ex0 * vx0), "f"(ex0 * vy0), "f"(0.f));
        asm volatile("red.global.add.v4.f32 [%0], {%1, %2, %3, %4};"
                     :: "l"(&g_acc[rr.y]), "f"(ex1), "f"(ex1 * vx1), "f"(ex1 * vy1), "f"(0.f));
        asm volatile("red.global.add.v4.f32 [%0], {%1, %2, %3, %4};"
                     :: "l"(&g_acc[rr.z]), "f"(ex2), "f"(ex2 * vx2), "f"(ex2 * vy2), "f"(0.f));
        asm volatile("red.global.add.v4.f32 [%0], {%1, %2, %3, %4};"
                     :: "l"(&g_acc[rr.w]), "f"(ex3), "f"(ex3 * vx3), "f"(ex3 * vy3), "f"(0.f));
    }

    // Release the dependent node_kernel launch as soon as this CTA's work
    // is issued (reds drain asynchronously; node's gridDependencySynchronize
    // still waits for full completion/visibility).
    cudaTriggerProgrammaticLaunchCompletion();
}

// One node's epilogue (depth mix + exp map + mobius add)
__device__ __forceinline__ float2 node_one(float4 acc, float2 xx,
                                           float k, float ang, float eta) {
    float inv_dn = __frcp_rn(fmaxf(acc.x, 1e-15f));
    float mx = acc.y * inv_dn;
    float my = acc.z * inv_dn;

    float sa, ca;
    __sincosf(ang, &sa, &ca);
    float tx = k * (ca * mx - sa * my);
    float ty = k * (sa * mx + ca * my);

    float wx = eta * tx;
    float wy = eta * ty;
    float wn2 = fmaxf(wx * wx + wy * wy, 1e-30f);
    float inv_wn = rsqrtf(wn2);
    float wn = wn2 * inv_wn;
    float aa = xx.x * xx.x + xx.y * xx.y;
    float lam = 2.f * __frcp_rn(fmaxf(1.f - aa, 1e-15f));
    // tanh(z) for z >= 0 via exp identity: accurate (~2^-22) and fast (MUFU.EX2)
    float z2 = lam * wn;                 // = 2*z
    float th = 1.f - 2.f * __frcp_rn(__expf(z2) + 1.f);
    float sx = th * wx * inv_wn;
    float sy = th * wy * inv_wn;

    float ab = xx.x * sx + xx.y * sy;
    float bb = sx * sx + sy * sy;
    float na = 1.f + 2.f * ab + bb;
    float nb = 1.f - aa;
    float den = fmaxf(1.f + 2.f * ab + aa * bb, 1e-15f);
    float inv_den = __frcp_rn(den);
    return make_float2((na * xx.x + nb * sx) * inv_den,
                       (na * xx.y + nb * sy) * inv_den);
}

__global__ void __launch_bounds__(256)
node_kernel(const float2* __restrict__ x,
            const int* __restrict__ depth,
            const float* __restrict__ eta_p,
            const float* __restrict__ depth_scale,
            const float* __restrict__ depth_theta,
            float2* __restrict__ out,
            int n) {
    int t = blockIdx.x * blockDim.x + threadIdx.x;
    int i0 = 2 * t;
    int i1 = 2 * t + 1;
    if (i0 >= n) return;
    bool two = (i1 < n);

    // ---- Independent loads: issued BEFORE waiting on the edge kernel ----
    float2 xx0 = __ldg(x + i0);
    float2 xx1 = two ? __ldg(x + i1) : xx0;
    int d0 = min(max(__ldg(depth + i0), 0), 511);
    int d1 = two ? min(max(__ldg(depth + i1), 0), 511) : d0;
    float eta = __ldg(eta_p);
    float k0 = __ldg(depth_scale + d0);
    float k1 = __ldg(depth_scale + d1);
    float a0 = __ldg(depth_theta + d0);
    float a1 = __ldg(depth_theta + d1);

    // ---- Wait for edge kernel completion (reds visible after this) ----
    cudaGridDependencySynchronize();

    float4 acc0 = g_acc[i0];
    float4 acc1 = two ? g_acc[i1] : acc0;

    // Re-zero the accumulator for the next invocation (self-cleaning).
    const float4 Z = make_float4(0.f, 0.f, 0.f, 0.f);
    g_acc[i0] = Z;
    if (two) g_acc[i1] = Z;

    float2 o0 = node_one(acc0, xx0, k0, a0, eta);
    float2 o1 = node_one(acc1, xx1, k1, a1, eta);

    out[i0] = o0;
    if (two) out[i1] = o1;
}

extern "C" void kernel_launch(void* const* d_in, const int* in_sizes, int n_in,
                              void* d_out, int out_size) {
    const float2* x  = (const float2*)d_in[0];
    const int* ei    = (const int*)d_in[1];
    const int* depth = (const int*)d_in[2];
    const float* W1  = (const float*)d_in[3];
    const float* b1  = (const float*)d_in[4];
    const float* W2  = (const float*)d_in[5];
    const float* eta = (const float*)d_in[6];
    const float* dsc = (const float*)d_in[7];
    const float* dth = (const float*)d_in[8];
    float2* out = (float2*)d_out;

    int N = in_sizes[0] / 2;
    int E = in_sizes[1] / 2;

    edge_kernel<<<1184, 256>>>(x, (const int4*)ei, (const int4*)(ei + E),
                               W1, b1, W2, E);

    // node_kernel with Programmatic Dependent Launch: overlaps its independent
    // load phase with the edge kernel's tail drain.
    int threads_needed = (N + 1) / 2;
    cudaLaunchConfig_t cfg = {};
    cfg.gridDim = dim3((threads_needed + 255) / 256, 1, 1);
    cfg.blockDim = dim3(256, 1, 1);
    cfg.dynamicSmemBytes = 0;
    cfg.stream = 0;
    cudaLaunchAttribute at[1];
    at[0].id = cudaLaunchAttributeProgrammaticStreamSerialization;
    at[0].val.programmaticStreamSerializationAllowed = 1;
    cfg.attrs = at;
    cfg.numAttrs = 1;
    cudaLaunchKernelEx(&cfg, node_kernel, x, depth, eta, dsc, dth, out, N);
}

// round 12
// speedup vs baseline: 1.0178x; 1.0178x over previous
#include <cuda_runtime.h>
#include <cuda_bf16.h>
#include <cstdint>

#define N_NODES 200000
#define ATTD 16

// Per-node accumulator: {sum_exp, sum_exp*vx, sum_exp*vy, pad}
// Zero-initialized at module load; node_kernel re-zeroes after consuming,
// so every kernel_launch invocation starts from a zeroed accumulator.
__device__ float4 g_acc[N_NODES];

// ---------- packed f32x2 helpers ----------
typedef unsigned long long f2;

__device__ __forceinline__ f2 pk(float a, float b) {
    f2 r; asm("mov.b64 %0, {%1, %2};" : "=l"(r) : "f"(a), "f"(b)); return r;
}
__device__ __forceinline__ void upk(f2 v, float& a, float& b) {
    asm("mov.b64 {%0, %1}, %2;" : "=f"(a), "=f"(b) : "l"(v));
}
__device__ __forceinline__ f2 fma2(f2 a, f2 b, f2 c) {
    f2 r; asm("fma.rn.f32x2 %0, %1, %2, %3;" : "=l"(r) : "l"(a), "l"(b), "l"(c)); return r;
}
__device__ __forceinline__ f2 mul2(f2 a, f2 b) {
    f2 r; asm("mul.rn.f32x2 %0, %1, %2;" : "=l"(r) : "l"(a), "l"(b)); return r;
}
__device__ __forceinline__ f2 add2(f2 a, f2 b) {
    f2 r; asm("add.rn.f32x2 %0, %1, %2;" : "=l"(r) : "l"(a), "l"(b)); return r;
}
__device__ __forceinline__ float tanh_ap(float x) {
    float y; asm("tanh.approx.f32 %0, %1;" : "=f"(y) : "f"(x)); return y;
}
__device__ __forceinline__ float rcp_ap(float x) {
    float y; asm("rcp.approx.f32 %0, %1;" : "=f"(y) : "f"(x)); return y;
}
__device__ __forceinline__ float rsqrt_ap(float x) {
    float y; asm("rsqrt.approx.f32 %0, %1;" : "=f"(y) : "f"(x)); return y;
}

struct EdgePair {
    f2 VX, VY;      // tangent vectors for 2 edges
};

// log-map for 2 edges packed in f32x2
__device__ __forceinline__ EdgePair logmap2(float2 xi0, float2 xi1,
                                            float2 xj0, float2 xj1) {
    const f2 ONE  = pk(1.f, 1.f);
    const f2 NEG1 = pk(-1.f, -1.f);
    const f2 TWO  = pk(2.f, 2.f);

    f2 AX  = pk(-xi0.x, -xi1.x);
    f2 AY  = pk(-xi0.y, -xi1.y);
    f2 XJX = pk(xj0.x, xj1.x);
    f2 XJY = pk(xj0.y, xj1.y);

    f2 DN = fma2(AY, XJY, mul2(AX, XJX));
    f2 AA = fma2(AY, AY, mul2(AX, AX));
    f2 BB = fma2(XJY, XJY, mul2(XJX, XJX));
    f2 NA = fma2(TWO, DN, add2(BB, ONE));       // 1 + 2 a.b + |b|^2
    f2 NB = fma2(AA, NEG1, ONE);                // 1 - |xi|^2  > 0.75, no clamp
    f2 DEN = fma2(TWO, DN, fma2(AA, BB, ONE));  // > 0.5, no clamp

    float d0, d1;
    upk(DEN, d0, d1);
    f2 IDEN = pk(rcp_ap(d0), rcp_ap(d1));

    f2 UX = mul2(fma2(NA, AX, mul2(NB, XJX)), IDEN);
    f2 UY = mul2(fma2(NA, AY, mul2(NB, XJY)), IDEN);

    f2 UN2 = fma2(UY, UY, mul2(UX, UX));
    float un20, un21;
    upk(UN2, un20, un21);
    un20 = fmaxf(un20, 1e-30f);
    un21 = fmaxf(un21, 1e-30f);
    float ir0 = rsqrt_ap(un20), ir1 = rsqrt_ap(un21);
    float z0 = fminf(un20 * ir0, 1.f - 1e-5f);
    float z1 = fminf(un21 * ir1, 1.f - 1e-5f);
    float at0 = 0.5f * __logf((1.f + z0) * rcp_ap(1.f - z0));  // atanh
    float at1 = 0.5f * __logf((1.f + z1) * rcp_ap(1.f - z1));

    f2 FACT = mul2(mul2(NB, pk(at0, at1)), pk(ir0, ir1));
    EdgePair ep;
    ep.VX = mul2(FACT, UX);
    ep.VY = mul2(FACT, UY);
    return ep;
}

__global__ void __launch_bounds__(256)
edge_kernel(const float2* __restrict__ x,
            const int4* __restrict__ row4,
            const int4* __restrict__ col4,
            const float* __restrict__ W1,
            const float* __restrict__ b1,
            const float* __restrict__ W2,
            int E) {
    // Broadcast-packed weights in shared memory (LDS.64 broadcast, conflict-free)
    __shared__ f2 sw1x[ATTD], sw1y[ATTD], sb1[ATTD], shw2[ATTD];
    if (threadIdx.x < ATTD) {
        int k = threadIdx.x;
        float a = __ldg(W1 + k);
        float b = __ldg(W1 + ATTD + k);
        float c = __ldg(b1 + k);
        float d = 0.5f * __ldg(W2 + k);
        sw1x[k] = pk(a, a);
        sw1y[k] = pk(b, b);
        sb1[k]  = pk(c, c);
        shw2[k] = pk(d, d);
    }
    __syncthreads();

    const f2 G0 = pk(0.7978845608028654f, 0.7978845608028654f);
    const f2 G1 = pk(0.0356774081363f, 0.0356774081363f);  // G0*0.044715

    int nquads = E >> 2;   // E divisible by 4
    int stride = gridDim.x * blockDim.x;
    for (int i = blockIdx.x * blockDim.x + threadIdx.x; i < nquads; i += stride) {
        int4 rr = __ldg(row4 + i);
        int4 cc = __ldg(col4 + i);

        // 8 independent gathers issued up front (L2-resident, MLP=8)
        float2 xiA = __ldg(x + rr.x);
        float2 xiB = __ldg(x + rr.y);
        float2 xiC = __ldg(x + rr.z);
        float2 xiD = __ldg(x + rr.w);
        float2 xjA = __ldg(x + cc.x);
        float2 xjB = __ldg(x + cc.y);
        float2 xjC = __ldg(x + cc.z);
        float2 xjD = __ldg(x + cc.w);

        EdgePair p0 = logmap2(xiA, xiB, xjA, xjB);
        EdgePair p1 = logmap2(xiC, xiD, xjC, xjD);

        // ---- MLP scores: two packed pipelines interleaved ----
        f2 S0 = pk(0.f, 0.f);
        f2 S1 = pk(0.f, 0.f);
#pragma unroll
        for (int k = 0; k < ATTD; k++) {
            f2 w1xk = sw1x[k], w1yk = sw1y[k], b1k = sb1[k], w2k = shw2[k];
            f2 PRE0 = fma2(p0.VX, w1xk, fma2(p0.VY, w1yk, b1k));
            f2 PRE1 = fma2(p1.VX, w1xk, fma2(p1.VY, w1yk, b1k));
            f2 ARG0 = mul2(fma2(mul2(PRE0, PRE0), G1, G0), PRE0);
            f2 ARG1 = mul2(fma2(mul2(PRE1, PRE1), G1, G0), PRE1);
            float a0, a1, a2, a3;
            upk(ARG0, a0, a1);
            upk(ARG1, a2, a3);
            f2 TH0 = pk(tanh_ap(a0), tanh_ap(a1));
            f2 TH1 = pk(tanh_ap(a2), tanh_ap(a3));
            f2 T0 = mul2(PRE0, w2k);
            f2 T1 = mul2(PRE1, w2k);
            S0 = add2(S0, T0);
            S1 = add2(S1, T1);
            S0 = fma2(T0, TH0, S0);
            S1 = fma2(T1, TH1, S1);
        }

        float s0, s1, s2, s3;
        upk(S0, s0, s1);
        upk(S1, s2, s3);
        float vx0, vx1, vx2, vx3, vy0, vy1, vy2, vy3;
        upk(p0.VX, vx0, vx1);
        upk(p0.VY, vy0, vy1);
        upk(p1.VX, vx2, vx3);
        upk(p1.VY, vy2, vy3);

        float ex0 = __expf(s0);
        float ex1 = __expf(s1);
        float ex2 = __expf(s2);
        float ex3 = __expf(s3);

        asm volatile("red.global.add.v4.f32 [%0], {%1, %2, %3, %4};"
                     :: "l"(&g_acc[rr.x]), "f"(ex0), "f"(ex0 * vx0), "f"(ex0 * vy0), "f"(0.f));
        asm volatile("red.global.add.v4.f32 [%0], {%1, %2, %3, %4};"
                     :: "l"(&g_acc[rr.y]), "f"(ex1), "f"(ex1 * vx1), "f"(ex1 * vy1), "f"(0.f));
        asm volatile("red.global.add.v4.f32 [%0], {%1, %2, %3, %4};"
                     :: "l"(&g_acc[rr.z]), "f"(ex2), "f"(ex2 * vx2), "f"(ex2 * vy2), "f"(0.f));
        asm volatile("red.global.add.v4.f32 [%0], {%1, %2, %3, %4};"
                     :: "l"(&g_acc[rr.w]), "f"(ex3), "f"(ex3 * vx3), "f"(ex3 * vy3), "f"(0.f));
    }

    cudaTriggerProgrammaticLaunchCompletion();
}

// One node's epilogue (depth mix + exp map + mobius add)
__device__ __forceinline__ float2 node_one(float4 acc, float2 xx,
                                           float k, float ang, float eta) {
    float inv_dn = __frcp_rn(fmaxf(acc.x, 1e-15f));
    float mx = acc.y * inv_dn;
    float my = acc.z * inv_dn;

    float sa, ca;
    __sincosf(ang, &sa, &ca);
    float tx = k * (ca * mx - sa * my);
    float ty = k * (sa * mx + ca * my);

    float wx = eta * tx;
    float wy = eta * ty;
    float wn2 = fmaxf(wx * wx + wy * wy, 1e-30f);
    float inv_wn = rsqrtf(wn2);
    float wn = wn2 * inv_wn;
    float aa = xx.x * xx.x + xx.y * xx.y;
    float lam = 2.f * __frcp_rn(fmaxf(1.f - aa, 1e-15f));
    // tanh(z) for z >= 0 via exp identity: accurate (~2^-22) and fast (MUFU.EX2)
    float z2 = lam * wn;                 // = 2*z
    float th = 1.f - 2.f * __frcp_rn(__expf(z2) + 1.f);
    float sx = th * wx * inv_wn;
    float sy = th * wy * inv_wn;

    float ab = xx.x * sx + xx.y * sy;
    float bb = sx * sx + sy * sy;
    float na = 1.f + 2.f * ab + bb;
    float nb = 1.f - aa;
    float den = fmaxf(1.f + 2.f * ab + aa * bb, 1e-15f);
    float inv_den = __frcp_rn(den);
    return make_float2((na * xx.x + nb * sx) * inv_den,
                       (na * xx.y + nb * sy) * inv_den);
}

__global__ void __launch_bounds__(256)
node_kernel(const float2* __restrict__ x,
            const int* __restrict__ depth,
            const float* __restrict__ eta_p,
            const float* __restrict__ depth_scale,
            const float* __restrict__ depth_theta,
            float2* __restrict__ out,
            int n) {
    int i = blockIdx.x * blockDim.x + threadIdx.x;
    if (i >= n) return;

    // Independent loads first (before the grid-dependency wait)
    float2 xx = __ldg(x + i);
    int d = min(max(__ldg(depth + i), 0), 511);
    float eta = __ldg(eta_p);
    float k = __ldg(depth_scale + d);
    float ang = __ldg(depth_theta + d);

    cudaGridDependencySynchronize();

    float4 acc = g_acc[i];
    // Re-zero for the next invocation (self-cleaning).
    g_acc[i] = make_float4(0.f, 0.f, 0.f, 0.f);

    out[i] = node_one(acc, xx, k, ang, eta);
}

extern "C" void kernel_launch(void* const* d_in, const int* in_sizes, int n_in,
                              void* d_out, int out_size) {
    const float2* x  = (const float2*)d_in[0];
    const int* ei    = (const int*)d_in[1];
    const int* depth = (const int*)d_in[2];
    const float* W1  = (const float*)d_in[3];
    const float* b1  = (const float*)d_in[4];
    const float* W2  = (const float*)d_in[5];
    const float* eta = (const float*)d_in[6];
    const float* dsc = (const float*)d_in[7];
    const float* dth = (const float*)d_in[8];
    float2* out = (float2*)d_out;

    int N = in_sizes[0] / 2;
    int E = in_sizes[1] / 2;

    // Size the edge grid to exactly ONE resident wave: perfectly balanced
    // persistent CTAs, no fractional-wave tail. (Host-side queries are
    // graph-capture-safe and deterministic.)
    int dev = 0;
    cudaGetDevice(&dev);
    int sms = 148;
    cudaDeviceGetAttribute(&sms, cudaDevAttrMultiProcessorCount, dev);
    int bpm = 4;
    cudaOccupancyMaxActiveBlocksPerMultiprocessor(&bpm, edge_kernel, 256, 0);
    if (bpm < 1) bpm = 1;
    int egrid = sms * bpm;
    int nquads = E >> 2;
    int maxg = (nquads + 255) / 256;
    if (egrid > maxg) egrid = maxg;

    edge_kernel<<<egrid, 256>>>(x, (const int4*)ei, (const int4*)(ei + E),
                                W1, b1, W2, E);

    // node_kernel: 1 node/thread for maximal thread-level parallelism; PDL
    // lets its independent loads issue during the edge kernel's drain.
    cudaLaunchConfig_t cfg = {};
    cfg.gridDim = dim3((N + 255) / 256, 1, 1);
    cfg.blockDim = dim3(256, 1, 1);
    cfg.dynamicSmemBytes = 0;
    cfg.stream = 0;
    cudaLaunchAttribute at[1];
    at[0].id = cudaLaunchAttributeProgrammaticStreamSerialization;
    at[0].val.programmaticStreamSerializationAllowed = 1;
    cfg.attrs = at;
    cfg.numAttrs = 1;
    cudaLaunchKernelEx(&cfg, node_kernel, x, depth, eta, dsc, dth, out, N);
}